// round 7
// baseline (speedup 1.0000x reference)
#include <cuda_runtime.h>
#include <cfloat>

// ChamferDistance: x,y = [16, 4096, 3] fp32 -> scalar
// R7: exact grid-pruned NN. db side bucketed into a 32x32 grid over (y,z) in
//     shared; each query scans Chebyshev rings of cells outward with
//     conservative lower-bound tests -> ~15x fewer distance evaluations than
//     brute force. Exact (bounds conservative) and deterministic (min is
//     order-independent, so atomic scatter order inside cells is irrelevant).

#define NB      16
#define NPTS    4096
#define SPLITS  4
#define QPB     (NPTS / SPLITS)   // 1024 queries per block
#define THREADS 256
#define PPT     (QPB / THREADS)   // 4 queries per thread
#define NBLOCKS (NB * 2 * SPLITS) // 128
#define NCY     32
#define NCZ     32
#define NCELL   (NCY * NCZ)

__device__ float g_partial[NBLOCKS];
__device__ unsigned int g_ticket;   // zero-init; reset by last block each run

struct SmemLayout {
    float4 pts[NPTS];        // cell-sorted db points (x,y,z,|p|^2)
    int    cnt[NCELL];
    int    off[NCELL];
    int    cur[NCELL];
    int    part[THREADS];    // block scan workspace
    float  mm[4][THREADS / 32]; // warp partials: ymin,ymax,zmin,zmax
    float  redf[THREADS / 32];
    float  ymin, ymax, zmin, zmax;
    bool   amlast;
};

__global__ __launch_bounds__(THREADS, 1) void chamfer_kernel(
    const float* __restrict__ x, const float* __restrict__ y,
    float* __restrict__ out)
{
    extern __shared__ char sraw[];
    SmemLayout* s = (SmemLayout*)sraw;

    const int tid = threadIdx.x;
    const int wid = tid >> 5, lid = tid & 31;
    const int dir = blockIdx.y;       // 0: query=x, db=y ; 1: query=y, db=x
    const int b   = blockIdx.z;
    const float* __restrict__ q  = (dir ? y : x) + (size_t)b * NPTS * 3;
    const float* __restrict__ db = (dir ? x : y) + (size_t)b * NPTS * 3;

    // ---- Pass A: (y,z) min/max of db ----
    float lymin = FLT_MAX, lymax = -FLT_MAX, lzmin = FLT_MAX, lzmax = -FLT_MAX;
    for (int j = tid; j < NPTS; j += THREADS) {
        float py = db[3 * j + 1], pz = db[3 * j + 2];
        lymin = fminf(lymin, py); lymax = fmaxf(lymax, py);
        lzmin = fminf(lzmin, pz); lzmax = fmaxf(lzmax, pz);
    }
#pragma unroll
    for (int o = 16; o > 0; o >>= 1) {
        lymin = fminf(lymin, __shfl_xor_sync(0xFFFFFFFFu, lymin, o));
        lymax = fmaxf(lymax, __shfl_xor_sync(0xFFFFFFFFu, lymax, o));
        lzmin = fminf(lzmin, __shfl_xor_sync(0xFFFFFFFFu, lzmin, o));
        lzmax = fmaxf(lzmax, __shfl_xor_sync(0xFFFFFFFFu, lzmax, o));
    }
    if (lid == 0) {
        s->mm[0][wid] = lymin; s->mm[1][wid] = lymax;
        s->mm[2][wid] = lzmin; s->mm[3][wid] = lzmax;
    }
    // zero cell counts while we're here
    for (int c = tid; c < NCELL; c += THREADS) s->cnt[c] = 0;
    __syncthreads();
    if (tid == 0) {
        float a0 = FLT_MAX, a1 = -FLT_MAX, a2 = FLT_MAX, a3 = -FLT_MAX;
#pragma unroll
        for (int w = 0; w < THREADS / 32; w++) {
            a0 = fminf(a0, s->mm[0][w]); a1 = fmaxf(a1, s->mm[1][w]);
            a2 = fminf(a2, s->mm[2][w]); a3 = fmaxf(a3, s->mm[3][w]);
        }
        s->ymin = a0; s->ymax = a1; s->zmin = a2; s->zmax = a3;
    }
    __syncthreads();

    const float ymin = s->ymin, ymax = s->ymax;
    const float zmin = s->zmin, zmax = s->zmax;
    const float cwy  = fmaxf((ymax - ymin) / NCY, 1e-20f);
    const float cwz  = fmaxf((zmax - zmin) / NCZ, 1e-20f);
    const float invy = 1.0f / cwy, invz = 1.0f / cwz;
    const float cwmin = fminf(cwy, cwz);

    // ---- Pass B: count ----
    for (int j = tid; j < NPTS; j += THREADS) {
        float py = db[3 * j + 1], pz = db[3 * j + 2];
        int cy = min(max((int)((py - ymin) * invy), 0), NCY - 1);
        int cz = min(max((int)((pz - zmin) * invz), 0), NCZ - 1);
        atomicAdd(&s->cnt[cy * NCZ + cz], 1);
    }
    __syncthreads();

    // ---- Exclusive prefix sum over 1024 counts (4 per thread + block scan) ----
    {
        int base4 = tid * 4;
        int sum = s->cnt[base4] + s->cnt[base4 + 1] + s->cnt[base4 + 2] + s->cnt[base4 + 3];
        s->part[tid] = sum;
        __syncthreads();
        for (int o = 1; o < THREADS; o <<= 1) {
            int v = (tid >= o) ? s->part[tid - o] : 0;
            __syncthreads();
            s->part[tid] += v;
            __syncthreads();
        }
        int run = (tid > 0) ? s->part[tid - 1] : 0;
#pragma unroll
        for (int u = 0; u < 4; u++) {
            s->off[base4 + u] = run;
            s->cur[base4 + u] = run;
            run += s->cnt[base4 + u];
        }
    }
    __syncthreads();

    // ---- Pass C: scatter (cell-sorted, intra-cell order irrelevant) ----
    for (int j = tid; j < NPTS; j += THREADS) {
        float px = db[3 * j + 0], py = db[3 * j + 1], pz = db[3 * j + 2];
        int cy = min(max((int)((py - ymin) * invy), 0), NCY - 1);
        int cz = min(max((int)((pz - zmin) * invz), 0), NCZ - 1);
        int pos = atomicAdd(&s->cur[cy * NCZ + cz], 1);
        s->pts[pos] = make_float4(px, py, pz, fmaf(px, px, fmaf(py, py, pz * pz)));
    }
    __syncthreads();

    // ---- Queries: ring search over cells ----
    float ssum = 0.0f;
    const int qbase = blockIdx.x * QPB + tid * PPT;
#pragma unroll 1
    for (int p = 0; p < PPT; p++) {
        const int i = qbase + p;
        const float px = q[3 * i + 0], py = q[3 * i + 1], pz = q[3 * i + 2];
        const float q2 = fmaf(px, px, fmaf(py, py, pz * pz));
        const float n0 = -2.0f * px, n1 = -2.0f * py, n2 = -2.0f * pz;

        const int cy = min(max((int)((py - ymin) * invy), 0), NCY - 1);
        const int cz = min(max((int)((pz - zmin) * invz), 0), NCZ - 1);
        const float ey = fmaxf(0.0f, fmaxf(ymin - py, py - ymax));
        const float ez = fmaxf(0.0f, fmaxf(zmin - pz, pz - zmax));
        const float e  = sqrtf(ey * ey + ez * ez);

        float bestt = FLT_MAX;   // best (d - q2); d = bestt + q2 >= 0

        for (int k = 0; k < 64; k++) {
            if (k > 0) {
                float lb = (float)(k - 1) * cwmin - e;
                if (lb > 0.0f && lb * lb >= bestt + q2) break;
            }
            const int ylo = max(cy - k, 0), yhi = min(cy + k, NCY - 1);
            const int zlo = max(cz - k, 0), zhi = min(cz + k, NCZ - 1);

            for (int iy = ylo; iy <= yhi; iy++) {
                const bool edge_y = (iy == cy - k) || (iy == cy + k);
                int izA, izB;
                if (edge_y) { izA = zlo; izB = zhi; }
                else        { izA = cz - k; izB = cz + k; }  // only the two z-edges
                for (int iz = izA; iz <= izB; iz += (edge_y ? 1 : (izB - izA > 0 ? izB - izA : 1))) {
                    if (iz < 0 || iz >= NCZ) continue;
                    const int c = iy * NCZ + iz;
                    const int n = s->cnt[c];
                    if (n == 0) continue;
                    if (k > 0) {  // per-cell planar lower bound
                        const float cyl = ymin + iy * cwy;
                        const float czl = zmin + iz * cwz;
                        const float dy = fmaxf(0.0f, fmaxf(cyl - py, py - (cyl + cwy)));
                        const float dz = fmaxf(0.0f, fmaxf(czl - pz, pz - (czl + cwz)));
                        if (dy * dy + dz * dz >= bestt + q2) continue;
                    }
                    int idx = s->off[c];
                    for (int u = 0; u < n; u++) {
                        const float4 v = s->pts[idx + u];
                        const float t = fmaf(n0, v.x, fmaf(n1, v.y, fmaf(n2, v.z, v.w)));
                        bestt = fminf(bestt, t);
                    }
                }
            }
            if (ylo == 0 && yhi == NCY - 1 && zlo == 0 && zhi == NCZ - 1) break;
        }
        ssum += bestt + q2;
    }

    // ---- Block reduction (fixed order -> deterministic) ----
#pragma unroll
    for (int o = 16; o > 0; o >>= 1) ssum += __shfl_down_sync(0xFFFFFFFFu, ssum, o);
    if (lid == 0) s->redf[wid] = ssum;
    __syncthreads();
    if (tid == 0) {
        float t = 0.0f;
#pragma unroll
        for (int w = 0; w < THREADS / 32; w++) t += s->redf[w];
        const int lin = blockIdx.x + SPLITS * (blockIdx.y + 2 * blockIdx.z);
        g_partial[lin] = t;
        __threadfence();
        unsigned int old = atomicAdd(&g_ticket, 1u);
        s->amlast = (old == NBLOCKS - 1);
    }
    __syncthreads();

    if (s->amlast) {
        float v = (tid < NBLOCKS) ? g_partial[tid] : 0.0f;
#pragma unroll
        for (int o = 16; o > 0; o >>= 1) v += __shfl_down_sync(0xFFFFFFFFu, v, o);
        if (lid == 0) s->redf[wid] = v;
        __syncthreads();
        if (tid == 0) {
            float t = 0.0f;
#pragma unroll
            for (int w = 0; w < THREADS / 32; w++) t += s->redf[w];
            out[0] = t * (1.0f / ((float)NB * (float)NPTS));
            g_ticket = 0;   // reset for next graph replay
        }
    }
}

extern "C" void kernel_launch(void* const* d_in, const int* in_sizes, int n_in,
                              void* d_out, int out_size)
{
    const float* x = (const float*)d_in[0];
    const float* y = (const float*)d_in[1];
    float* out = (float*)d_out;

    const int smem = (int)sizeof(SmemLayout);   // ~79 KB
    cudaFuncSetAttribute(chamfer_kernel,
                         cudaFuncAttributeMaxDynamicSharedMemorySize, smem);

    dim3 grid(SPLITS, 2, NB);
    chamfer_kernel<<<grid, THREADS, smem>>>(x, y, out);
}